// round 2
// baseline (speedup 1.0000x reference)
#include <cuda_runtime.h>
#include <cuda_bf16.h>
#include <cstdint>
#include <cstddef>

#define VOCAB 2048
#define EMB 256
#define KTOT 2304          // EMB + VOCAB
#define NTOT 8192          // 4*VOCAB
#define BATCH 32
#define TSTEPS 8
#define LAT 128

#define NTILE 64
#define KTILE 32
#define NITER (KTOT / KTILE)   // 72
#define APAD 40                // bf16 elems per A smem row (32 + pad)
#define WPAD 72                // bf16 elems per W smem row (64 + pad)

// ---------------- scratch (device globals: no allocations allowed) ----------
__device__ __align__(16) __nv_bfloat16 g_W[(size_t)KTOT * NTOT];   // 37.75 MB bf16 weights
__device__ __align__(16) __nv_bfloat16 g_A[BATCH * KTOT];          // [emb | h] per row, bf16
__device__ __align__(16) float g_gates[BATCH * NTOT];              // GEMM output
__device__ float g_c[BATCH * VOCAB];
__device__ float g_h[BATCH * VOCAB];

// ---------------- weight conversion: fp32 (Wi ‖ Wh) -> bf16 -----------------
__global__ void convert_weights(const float* __restrict__ Wi,
                                const float* __restrict__ Wh) {
    size_t idx = ((size_t)blockIdx.x * blockDim.x + threadIdx.x) * 8;
    const size_t NI = (size_t)EMB * NTOT;   // 2,097,152 (divisible by 8)
    const float* src = (idx < NI) ? (Wi + idx) : (Wh + (idx - NI));
    float4 f0 = reinterpret_cast<const float4*>(src)[0];
    float4 f1 = reinterpret_cast<const float4*>(src)[1];
    __nv_bfloat162 b0 = __float22bfloat162_rn(make_float2(f0.x, f0.y));
    __nv_bfloat162 b1 = __float22bfloat162_rn(make_float2(f0.z, f0.w));
    __nv_bfloat162 b2 = __float22bfloat162_rn(make_float2(f1.x, f1.y));
    __nv_bfloat162 b3 = __float22bfloat162_rn(make_float2(f1.z, f1.w));
    uint4 pv;
    pv.x = *reinterpret_cast<unsigned*>(&b0);
    pv.y = *reinterpret_cast<unsigned*>(&b1);
    pv.z = *reinterpret_cast<unsigned*>(&b2);
    pv.w = *reinterpret_cast<unsigned*>(&b3);
    *reinterpret_cast<uint4*>(g_W + idx) = pv;
}

// ---------------- init: zero state, emb for step 1, out[:,0,:] = 0 ----------
__global__ void init_state(const int* __restrict__ tokens,
                           const float* __restrict__ E,
                           float* __restrict__ out) {
    int b = blockIdx.x, tid = threadIdx.x;   // 32 blocks x 256 threads
#pragma unroll
    for (int i = 0; i < 8; i++) {
        int n = tid + i * 256;
        g_c[b * VOCAB + n] = 0.f;
        g_h[b * VOCAB + n] = 0.f;
        g_A[b * KTOT + EMB + n] = __float2bfloat16(0.f);
    }
    int v = tokens[b * TSTEPS + 0];          // token column 1 (processed at step 1)
    g_A[b * KTOT + tid] = __float2bfloat16(E[(size_t)v * EMB + tid]);
    if (tid < LAT) out[(b * TSTEPS + 0) * LAT + tid] = 0.f;   // t=0 output is exactly 0
}

// ---------------- GEMM helpers ----------------------------------------------
__device__ __forceinline__ uint32_t smem_u32(const void* p) {
    return (uint32_t)__cvta_generic_to_shared(p);
}
__device__ __forceinline__ void cp_async16(uint32_t dst, const void* src) {
    asm volatile("cp.async.cg.shared.global [%0], [%1], 16;\n" :: "r"(dst), "l"(src));
}
__device__ __forceinline__ void ldsm_x4(uint32_t* r, uint32_t addr) {
    asm volatile("ldmatrix.sync.aligned.m8n8.x4.shared.b16 {%0,%1,%2,%3}, [%4];\n"
                 : "=r"(r[0]), "=r"(r[1]), "=r"(r[2]), "=r"(r[3]) : "r"(addr));
}
__device__ __forceinline__ void ldsm_x4_t(uint32_t* r, uint32_t addr) {
    asm volatile("ldmatrix.sync.aligned.m8n8.x4.trans.shared.b16 {%0,%1,%2,%3}, [%4];\n"
                 : "=r"(r[0]), "=r"(r[1]), "=r"(r[2]), "=r"(r[3]) : "r"(addr));
}
__device__ __forceinline__ void mma16816(float* d, const uint32_t* a, uint32_t b0, uint32_t b1) {
    asm volatile("mma.sync.aligned.m16n8k16.row.col.f32.bf16.bf16.f32 "
                 "{%0,%1,%2,%3}, {%4,%5,%6,%7}, {%8,%9}, {%0,%1,%2,%3};\n"
                 : "+f"(d[0]), "+f"(d[1]), "+f"(d[2]), "+f"(d[3])
                 : "r"(a[0]), "r"(a[1]), "r"(a[2]), "r"(a[3]), "r"(b0), "r"(b1));
}

__device__ __forceinline__ void issue_tile(__nv_bfloat16* As, __nv_bfloat16* Ws,
                                           int k0, int n0, int tid) {
    // A tile: 32 rows (m) x 32 k-elems = 64B/row -> 128 x 16B chunks
    {
        int m = tid >> 2, c = tid & 3;
        cp_async16(smem_u32(&As[m * APAD + c * 8]),
                   g_A + m * KTOT + k0 + c * 8);
    }
    // W tile: 32 rows (k) x 64 n-elems = 128B/row -> 256 x 16B chunks
#pragma unroll
    for (int j = 0; j < 2; j++) {
        int idx = tid + j * 128;
        int k = idx >> 3, c = idx & 7;
        cp_async16(smem_u32(&Ws[k * WPAD + c * 8]),
                   g_W + (size_t)(k0 + k) * NTOT + n0 + c * 8);
    }
}

// gates[32, 8192] = A[32, 2304] @ W[2304, 8192]   (bf16 in, fp32 accum)
__global__ __launch_bounds__(128, 1) void gemm_kernel() {
    __shared__ __align__(16) __nv_bfloat16 As[2][32 * APAD];
    __shared__ __align__(16) __nv_bfloat16 Ws[2][KTILE * WPAD];
    const int n0   = blockIdx.x * NTILE;
    const int tid  = threadIdx.x;
    const int lane = tid & 31, warp = tid >> 5;
    const int mh = warp & 1;        // m offset 0/16
    const int nh = warp >> 1;       // n offset 0/32 within tile

    float acc[4][4];
#pragma unroll
    for (int i = 0; i < 4; i++)
#pragma unroll
        for (int j = 0; j < 4; j++) acc[i][j] = 0.f;

    issue_tile(As[0], Ws[0], 0, n0, tid);
    asm volatile("cp.async.commit_group;\n");

    for (int it = 0; it < NITER; ++it) {
        if (it + 1 < NITER) issue_tile(As[(it + 1) & 1], Ws[(it + 1) & 1],
                                       (it + 1) * KTILE, n0, tid);
        asm volatile("cp.async.commit_group;\n");
        asm volatile("cp.async.wait_group 1;\n");
        __syncthreads();

        const __nv_bfloat16* as = As[it & 1];
        const __nv_bfloat16* ws = Ws[it & 1];
#pragma unroll
        for (int ks = 0; ks < 2; ++ks) {
            uint32_t a[4];
            {
                int row = mh * 16 + (lane & 15);
                int col = ks * 16 + (lane >> 4) * 8;
                ldsm_x4(a, smem_u32(&as[row * APAD + col]));
            }
#pragma unroll
            for (int ns = 0; ns < 2; ++ns) {
                uint32_t bq[4];
                int krow = ks * 16 + (lane & 15);
                int col  = nh * 32 + ns * 16 + (lane >> 4) * 8;
                ldsm_x4_t(bq, smem_u32(&ws[krow * WPAD + col]));
                mma16816(acc[ns * 2 + 0], a, bq[0], bq[1]);
                mma16816(acc[ns * 2 + 1], a, bq[2], bq[3]);
            }
        }
        __syncthreads();
    }

#pragma unroll
    for (int nt = 0; nt < 4; ++nt) {
        int row = mh * 16 + (lane >> 2);
        int col = n0 + nh * 32 + nt * 8 + (lane & 3) * 2;
        *reinterpret_cast<float2*>(&g_gates[(size_t)row * NTOT + col]) =
            make_float2(acc[nt][0], acc[nt][1]);
        *reinterpret_cast<float2*>(&g_gates[(size_t)(row + 8) * NTOT + col]) =
            make_float2(acc[nt][2], acc[nt][3]);
    }
}

// ---------------- LSTM update + masked softmax-prefix + output --------------
__device__ __forceinline__ float sigmoidf_(float x) { return 1.f / (1.f + expf(-x)); }

__global__ void step_update(const int* __restrict__ tokens,
                            const float* __restrict__ bias,
                            const float* __restrict__ E,
                            float* __restrict__ out, int t) {
    int b = blockIdx.x;                 // one block per batch row
    int tid = threadIdx.x;              // 256 threads
    int lane = tid & 31, wid = tid >> 5;
    __shared__ float red[32];

    int v = tokens[b * TSTEPS + (t - 1)];   // token processed this step (column t)
    int s = tokens[b * TSTEPS + t];         // gather target (column t+1)
    bool upd = (v != 0);

    float hv[8];
    float locmax = -1e30f;
#pragma unroll
    for (int i = 0; i < 8; i++) {
        int n = tid + i * 256;
        float gi = g_gates[(size_t)b * NTOT + n]             + bias[n];
        float gf = g_gates[(size_t)b * NTOT + VOCAB + n]     + bias[VOCAB + n];
        float gg = g_gates[(size_t)b * NTOT + 2 * VOCAB + n] + bias[2 * VOCAB + n];
        float go = g_gates[(size_t)b * NTOT + 3 * VOCAB + n] + bias[3 * VOCAB + n];
        float ia = sigmoidf_(gi), fa = sigmoidf_(gf);
        float ga = tanhf(gg),     oa = sigmoidf_(go);
        float cn = fa * g_c[b * VOCAB + n] + ia * ga;
        float hn = oa * tanhf(cn);
        float h;
        if (upd) { g_c[b * VOCAB + n] = cn; h = hn; g_h[b * VOCAB + n] = h; }
        else     { h = g_h[b * VOCAB + n]; }
        g_A[b * KTOT + EMB + n] = __float2bfloat16(h);   // feed next GEMM
        hv[i] = h;
        locmax = fmaxf(locmax, h);
    }

    // block max over 2048 h values
#pragma unroll
    for (int o = 16; o; o >>= 1) locmax = fmaxf(locmax, __shfl_xor_sync(0xffffffffu, locmax, o));
    if (lane == 0) red[wid] = locmax;
    __syncthreads();
    float m = red[0];
#pragma unroll
    for (int w = 1; w < 8; ++w) m = fmaxf(m, red[w]);
    __syncthreads();

    // Z = sum exp ; S = sum_{n<s} exp + 0.5*exp(h_s)
    float Z = 0.f, S = 0.f;
#pragma unroll
    for (int i = 0; i < 8; i++) {
        int n = tid + i * 256;
        float e = expf(hv[i] - m);
        Z += e;
        if (n < s) S += e;
        else if (n == s) S += 0.5f * e;
    }
#pragma unroll
    for (int o = 16; o; o >>= 1) {
        Z += __shfl_xor_sync(0xffffffffu, Z, o);
        S += __shfl_xor_sync(0xffffffffu, S, o);
    }
    if (lane == 0) { red[wid] = Z; red[8 + wid] = S; }
    __syncthreads();
    float Zt = 0.f, St = 0.f;
#pragma unroll
    for (int w = 0; w < 8; ++w) { Zt += red[w]; St += red[8 + w]; }

    // z[b, t, :] = 3*(cumsum_exclusive[s] + 0.5*p_s), broadcast over LAT
    if (tid < LAT) out[((size_t)b * TSTEPS + t) * LAT + tid] = 3.0f * St / Zt;

    // pre-stage embedding row for next step (token column t+1 == s)
    if (t < TSTEPS - 1)
        g_A[b * KTOT + tid] = __float2bfloat16(E[(size_t)s * EMB + tid]);
}

// ---------------- launch ----------------------------------------------------
extern "C" void kernel_launch(void* const* d_in, const int* in_sizes, int n_in,
                              void* d_out, int out_size) {
    const int* tokens = nullptr;
    const float *E = nullptr, *Wi = nullptr, *Wh = nullptr, *bias = nullptr;
    for (int i = 0; i < n_in; i++) {
        switch (in_sizes[i]) {
            case BATCH * TSTEPS:      tokens = (const int*)d_in[i];   break;  // 256
            case VOCAB * EMB:         E      = (const float*)d_in[i]; break;  // 524288
            case EMB * 4 * VOCAB:     Wi     = (const float*)d_in[i]; break;  // 2097152
            case VOCAB * 4 * VOCAB:   Wh     = (const float*)d_in[i]; break;  // 16777216
            case 4 * VOCAB:           bias   = (const float*)d_in[i]; break;  // 8192
        }
    }
    float* out = (float*)d_out;

    // fp32 -> bf16 weight pack (per replay; deterministic)
    convert_weights<<<(KTOT * NTOT) / 8 / 256, 256>>>(Wi, Wh);
    init_state<<<BATCH, 256>>>(tokens, E, out);

    for (int t = 1; t < TSTEPS; ++t) {
        gemm_kernel<<<NTOT / NTILE, 128>>>();
        step_update<<<BATCH, 256>>>(tokens, bias, E, out, t);
    }
}

// round 4
// speedup vs baseline: 1.2451x; 1.2451x over previous
#include <cuda_runtime.h>
#include <cuda_bf16.h>
#include <cstdint>
#include <cstddef>

#define VOCAB 2048
#define EMB 256
#define KTOT 2304          // EMB + VOCAB
#define NTOT 8192          // 4*VOCAB
#define BATCH 32
#define TSTEPS 8
#define LAT 128

#define NTILE 64
#define KTILE 32
#define NITER (KTOT / KTILE)   // 72
#define STAGES 4
#define APAD 40                // bf16 elems per A smem row (32 + pad)
#define WPAD 72                // bf16 elems per W smem row (64 + pad)

// ---------------- scratch (device globals: no allocations allowed) ----------
__device__ __align__(16) __nv_bfloat16 g_W[(size_t)KTOT * NTOT];   // 37.75 MB bf16 weights
__device__ __align__(16) __nv_bfloat16 g_A[BATCH * KTOT];          // [emb | h] per row, bf16
__device__ __align__(16) float g_gates[BATCH * NTOT];              // GEMM output
__device__ float g_c[BATCH * VOCAB];
__device__ float g_h[BATCH * VOCAB];

// ---------------- weight conversion: fp32 (Wi ‖ Wh) -> bf16 -----------------
__global__ void convert_weights(const float* __restrict__ Wi,
                                const float* __restrict__ Wh) {
    size_t idx = ((size_t)blockIdx.x * blockDim.x + threadIdx.x) * 8;
    const size_t NI = (size_t)EMB * NTOT;   // 2,097,152 (divisible by 8)
    const float* src = (idx < NI) ? (Wi + idx) : (Wh + (idx - NI));
    float4 f0 = reinterpret_cast<const float4*>(src)[0];
    float4 f1 = reinterpret_cast<const float4*>(src)[1];
    __nv_bfloat162 b0 = __float22bfloat162_rn(make_float2(f0.x, f0.y));
    __nv_bfloat162 b1 = __float22bfloat162_rn(make_float2(f0.z, f0.w));
    __nv_bfloat162 b2 = __float22bfloat162_rn(make_float2(f1.x, f1.y));
    __nv_bfloat162 b3 = __float22bfloat162_rn(make_float2(f1.z, f1.w));
    uint4 pv;
    pv.x = *reinterpret_cast<unsigned*>(&b0);
    pv.y = *reinterpret_cast<unsigned*>(&b1);
    pv.z = *reinterpret_cast<unsigned*>(&b2);
    pv.w = *reinterpret_cast<unsigned*>(&b3);
    *reinterpret_cast<uint4*>(g_W + idx) = pv;
}

// ---------------- init: zero state, emb for step 1, out[:,0,:] = 0 ----------
__global__ void init_state(const int* __restrict__ tokens,
                           const float* __restrict__ E,
                           float* __restrict__ out) {
    int b = blockIdx.x, tid = threadIdx.x;   // 32 blocks x 256 threads
#pragma unroll
    for (int i = 0; i < 8; i++) {
        int n = tid + i * 256;
        g_c[b * VOCAB + n] = 0.f;
        g_h[b * VOCAB + n] = 0.f;
        g_A[b * KTOT + EMB + n] = __float2bfloat16(0.f);
    }
    int v = tokens[b * TSTEPS + 0];          // token column 1 (processed at step 1)
    g_A[b * KTOT + tid] = __float2bfloat16(E[(size_t)v * EMB + tid]);
    if (tid < LAT) out[(b * TSTEPS + 0) * LAT + tid] = 0.f;   // t=0 output is exactly 0
}

// ---------------- GEMM helpers ----------------------------------------------
__device__ __forceinline__ uint32_t smem_u32(const void* p) {
    return (uint32_t)__cvta_generic_to_shared(p);
}
__device__ __forceinline__ void cp_async16(uint32_t dst, const void* src) {
    asm volatile("cp.async.cg.shared.global [%0], [%1], 16;\n" :: "r"(dst), "l"(src));
}
__device__ __forceinline__ void ldsm_x4(uint32_t* r, uint32_t addr) {
    asm volatile("ldmatrix.sync.aligned.m8n8.x4.shared.b16 {%0,%1,%2,%3}, [%4];\n"
                 : "=r"(r[0]), "=r"(r[1]), "=r"(r[2]), "=r"(r[3]) : "r"(addr));
}
__device__ __forceinline__ void ldsm_x4_t(uint32_t* r, uint32_t addr) {
    asm volatile("ldmatrix.sync.aligned.m8n8.x4.trans.shared.b16 {%0,%1,%2,%3}, [%4];\n"
                 : "=r"(r[0]), "=r"(r[1]), "=r"(r[2]), "=r"(r[3]) : "r"(addr));
}
__device__ __forceinline__ void mma16816(float* d, const uint32_t* a, uint32_t b0, uint32_t b1) {
    asm volatile("mma.sync.aligned.m16n8k16.row.col.f32.bf16.bf16.f32 "
                 "{%0,%1,%2,%3}, {%4,%5,%6,%7}, {%8,%9}, {%0,%1,%2,%3};\n"
                 : "+f"(d[0]), "+f"(d[1]), "+f"(d[2]), "+f"(d[3])
                 : "r"(a[0]), "r"(a[1]), "r"(a[2]), "r"(a[3]), "r"(b0), "r"(b1));
}

__device__ __forceinline__ void issue_tile(__nv_bfloat16* As, __nv_bfloat16* Ws,
                                           int k0, int n0, int tid) {
    // A tile: 32 rows (m) x 32 k-elems = 64B/row -> 128 x 16B chunks
    {
        int m = tid >> 2, c = tid & 3;
        cp_async16(smem_u32(&As[m * APAD + c * 8]),
                   g_A + m * KTOT + k0 + c * 8);
    }
    // W tile: 32 rows (k) x 64 n-elems = 128B/row -> 256 x 16B chunks
#pragma unroll
    for (int j = 0; j < 2; j++) {
        int idx = tid + j * 128;
        int k = idx >> 3, c = idx & 7;
        cp_async16(smem_u32(&Ws[k * WPAD + c * 8]),
                   g_W + (size_t)(k0 + k) * NTOT + n0 + c * 8);
    }
}

// gates[32, 8192] = A[32, 2304] @ W[2304, 8192]   (bf16 in, fp32 accum)
// 4-stage cp.async pipeline: keeps ~2 W-tiles (~9KB) of L2 traffic in flight/SM.
__global__ __launch_bounds__(128, 1) void gemm_kernel() {
    __shared__ __align__(16) __nv_bfloat16 As[STAGES][32 * APAD];
    __shared__ __align__(16) __nv_bfloat16 Ws[STAGES][KTILE * WPAD];
    const int n0   = blockIdx.x * NTILE;
    const int tid  = threadIdx.x;
    const int lane = tid & 31, warp = tid >> 5;
    const int mh = warp & 1;        // m offset 0/16
    const int nh = warp >> 1;       // n offset 0/32 within tile

    float acc[4][4];
#pragma unroll
    for (int i = 0; i < 4; i++)
#pragma unroll
        for (int j = 0; j < 4; j++) acc[i][j] = 0.f;

#pragma unroll
    for (int s = 0; s < STAGES - 1; ++s) {
        issue_tile(As[s], Ws[s], s * KTILE, n0, tid);
        asm volatile("cp.async.commit_group;\n");
    }

    for (int it = 0; it < NITER; ++it) {
        asm volatile("cp.async.wait_group %0;\n" :: "n"(STAGES - 2));
        __syncthreads();

        // prefetch stage it+3 into the buffer consumed at iter it-1
        if (it + STAGES - 1 < NITER)
            issue_tile(As[(it + STAGES - 1) & (STAGES - 1)],
                       Ws[(it + STAGES - 1) & (STAGES - 1)],
                       (it + STAGES - 1) * KTILE, n0, tid);
        asm volatile("cp.async.commit_group;\n");   // commit (possibly empty) to keep counts aligned

        const __nv_bfloat16* as = As[it & (STAGES - 1)];
        const __nv_bfloat16* ws = Ws[it & (STAGES - 1)];
#pragma unroll
        for (int ks = 0; ks < 2; ++ks) {
            uint32_t a[4];
            {
                int row = mh * 16 + (lane & 15);
                int col = ks * 16 + (lane >> 4) * 8;
                ldsm_x4(a, smem_u32(&as[row * APAD + col]));
            }
#pragma unroll
            for (int ns = 0; ns < 2; ++ns) {
                uint32_t bq[4];
                int krow = ks * 16 + (lane & 15);
                int col  = nh * 32 + ns * 16 + (lane >> 4) * 8;
                ldsm_x4_t(bq, smem_u32(&ws[krow * WPAD + col]));
                mma16816(acc[ns * 2 + 0], a, bq[0], bq[1]);
                mma16816(acc[ns * 2 + 1], a, bq[2], bq[3]);
            }
        }
    }

#pragma unroll
    for (int nt = 0; nt < 4; ++nt) {
        int row = mh * 16 + (lane >> 2);
        int col = n0 + nh * 32 + nt * 8 + (lane & 3) * 2;
        *reinterpret_cast<float2*>(&g_gates[(size_t)row * NTOT + col]) =
            make_float2(acc[nt][0], acc[nt][1]);
        *reinterpret_cast<float2*>(&g_gates[(size_t)(row + 8) * NTOT + col]) =
            make_float2(acc[nt][2], acc[nt][3]);
    }
}

// ---------------- LSTM update + masked softmax-prefix + output --------------
// Fast activations via MUFU (EX2 + RCP): rel err ~1e-6, vs libm's branchy paths.
__device__ __forceinline__ float fsig(float x) {
    return __fdividef(1.f, 1.f + __expf(-x));
}
__device__ __forceinline__ float ftanh(float x) {
    return __fdividef(2.f, 1.f + __expf(-2.f * x)) - 1.f;
}

__global__ void step_update(const int* __restrict__ tokens,
                            const float* __restrict__ bias,
                            const float* __restrict__ E,
                            float* __restrict__ out, int t) {
    int b = blockIdx.x;                 // one block per batch row
    int tid = threadIdx.x;              // 256 threads
    int lane = tid & 31, wid = tid >> 5;
    __shared__ float red[32];

    int v = tokens[b * TSTEPS + (t - 1)];   // token processed this step (column t)
    int s = tokens[b * TSTEPS + t];         // gather target (column t+1)
    bool upd = (v != 0);

    float hv[8];
    float locmax = -1e30f;
#pragma unroll
    for (int i = 0; i < 8; i++) {
        int n = tid + i * 256;
        float gi = g_gates[(size_t)b * NTOT + n]             + bias[n];
        float gf = g_gates[(size_t)b * NTOT + VOCAB + n]     + bias[VOCAB + n];
        float gg = g_gates[(size_t)b * NTOT + 2 * VOCAB + n] + bias[2 * VOCAB + n];
        float go = g_gates[(size_t)b * NTOT + 3 * VOCAB + n] + bias[3 * VOCAB + n];
        float ia = fsig(gi), fa = fsig(gf);
        float ga = ftanh(gg), oa = fsig(go);
        float cn = fa * g_c[b * VOCAB + n] + ia * ga;
        float hn = oa * ftanh(cn);
        float h;
        if (upd) { g_c[b * VOCAB + n] = cn; h = hn; g_h[b * VOCAB + n] = h; }
        else     { h = g_h[b * VOCAB + n]; }
        g_A[b * KTOT + EMB + n] = __float2bfloat16(h);   // feed next GEMM
        hv[i] = h;
        locmax = fmaxf(locmax, h);
    }

    // block max over 2048 h values
#pragma unroll
    for (int o = 16; o; o >>= 1) locmax = fmaxf(locmax, __shfl_xor_sync(0xffffffffu, locmax, o));
    if (lane == 0) red[wid] = locmax;
    __syncthreads();
    float m = red[0];
#pragma unroll
    for (int w = 1; w < 8; ++w) m = fmaxf(m, red[w]);
    __syncthreads();

    // Z = sum exp ; S = sum_{n<s} exp + 0.5*exp(h_s)
    float Z = 0.f, S = 0.f;
#pragma unroll
    for (int i = 0; i < 8; i++) {
        int n = tid + i * 256;
        float e = __expf(hv[i] - m);
        Z += e;
        if (n < s) S += e;
        else if (n == s) S += 0.5f * e;
    }
#pragma unroll
    for (int o = 16; o; o >>= 1) {
        Z += __shfl_xor_sync(0xffffffffu, Z, o);
        S += __shfl_xor_sync(0xffffffffu, S, o);
    }
    if (lane == 0) { red[wid] = Z; red[8 + wid] = S; }
    __syncthreads();
    float Zt = 0.f, St = 0.f;
#pragma unroll
    for (int w = 0; w < 8; ++w) { Zt += red[w]; St += red[8 + w]; }

    // z[b, t, :] = 3*(cumsum_exclusive[s] + 0.5*p_s), broadcast over LAT
    if (tid < LAT) out[((size_t)b * TSTEPS + t) * LAT + tid] = 3.0f * St / Zt;

    // pre-stage embedding row for next step (token column t+1 == s)
    if (t < TSTEPS - 1)
        g_A[b * KTOT + tid] = __float2bfloat16(E[(size_t)s * EMB + tid]);
}

// ---------------- launch ----------------------------------------------------
extern "C" void kernel_launch(void* const* d_in, const int* in_sizes, int n_in,
                              void* d_out, int out_size) {
    const int* tokens = nullptr;
    const float *E = nullptr, *Wi = nullptr, *Wh = nullptr, *bias = nullptr;
    for (int i = 0; i < n_in; i++) {
        switch (in_sizes[i]) {
            case BATCH * TSTEPS:      tokens = (const int*)d_in[i];   break;  // 256
            case VOCAB * EMB:         E      = (const float*)d_in[i]; break;  // 524288
            case EMB * 4 * VOCAB:     Wi     = (const float*)d_in[i]; break;  // 2097152
            case VOCAB * 4 * VOCAB:   Wh     = (const float*)d_in[i]; break;  // 16777216
            case 4 * VOCAB:           bias   = (const float*)d_in[i]; break;  // 8192
        }
    }
    float* out = (float*)d_out;

    // fp32 -> bf16 weight pack (per replay; deterministic)
    convert_weights<<<(KTOT * NTOT) / 8 / 256, 256>>>(Wi, Wh);
    init_state<<<BATCH, 256>>>(tokens, E, out);

    for (int t = 1; t < TSTEPS; ++t) {
        gemm_kernel<<<NTOT / NTILE, 128>>>();
        step_update<<<BATCH, 256>>>(tokens, bias, E, out, t);
    }
}

// round 5
// speedup vs baseline: 1.3802x; 1.1085x over previous
#include <cuda_runtime.h>
#include <cuda_bf16.h>
#include <cstdint>
#include <cstddef>

#define VOCAB 2048
#define EMB 256
#define KTOT 2304          // EMB + VOCAB
#define NTOT 8192          // 4*VOCAB
#define BATCH 32
#define TSTEPS 8
#define LAT 128

#define NBLK 128           // blocks; each owns 16 h-columns (x4 gate sections)
#define KTILE 32
#define NITER (KTOT / KTILE)   // 72
#define STAGES 4
#define APAD 40                // bf16 elems per A smem row (32 + pad)
#define WPAD 72                // bf16 elems per W smem row (64 + pad)
#define GPITCH 66              // float pitch for gate staging smem

// ---------------- scratch (device globals: no allocations allowed) ----------
__device__ __align__(16) __nv_bfloat16 g_W[(size_t)KTOT * NTOT];   // 37.75 MB bf16 weights
__device__ __align__(16) __nv_bfloat16 g_Ebf[VOCAB * EMB];         // bf16 embedding table
__device__ __align__(16) __nv_bfloat16 g_Hbf[2][BATCH * VOCAB];    // ping-pong h (bf16)
__device__ float g_c[BATCH * VOCAB];
__device__ float g_h[BATCH * VOCAB];
__device__ float g_partZ[BATCH * NBLK];
__device__ float g_partS[BATCH * NBLK];

// ---------------- conversion: Wi‖Wh -> bf16, E -> bf16 ----------------------
__global__ void convert_weights(const float* __restrict__ Wi,
                                const float* __restrict__ Wh,
                                const float* __restrict__ E) {
    size_t idx = ((size_t)blockIdx.x * blockDim.x + threadIdx.x) * 8;
    const size_t NW = (size_t)KTOT * NTOT;        // 18,874,368
    const size_t NI = (size_t)EMB * NTOT;         // 2,097,152
    const float* src;
    __nv_bfloat16* dst;
    if (idx < NW) {
        src = (idx < NI) ? (Wi + idx) : (Wh + (idx - NI));
        dst = g_W + idx;
    } else {
        size_t e = idx - NW;                      // < VOCAB*EMB
        src = E + e;
        dst = g_Ebf + e;
    }
    float4 f0 = reinterpret_cast<const float4*>(src)[0];
    float4 f1 = reinterpret_cast<const float4*>(src)[1];
    __nv_bfloat162 b0 = __float22bfloat162_rn(make_float2(f0.x, f0.y));
    __nv_bfloat162 b1 = __float22bfloat162_rn(make_float2(f0.z, f0.w));
    __nv_bfloat162 b2 = __float22bfloat162_rn(make_float2(f1.x, f1.y));
    __nv_bfloat162 b3 = __float22bfloat162_rn(make_float2(f1.z, f1.w));
    uint4 pv;
    pv.x = *reinterpret_cast<unsigned*>(&b0);
    pv.y = *reinterpret_cast<unsigned*>(&b1);
    pv.z = *reinterpret_cast<unsigned*>(&b2);
    pv.w = *reinterpret_cast<unsigned*>(&b3);
    *reinterpret_cast<uint4*>(dst) = pv;
}

// ---------------- init: zero state + out[:,0,:] -----------------------------
__global__ void init_state(float* __restrict__ out) {
    int b = blockIdx.x, tid = threadIdx.x;   // 32 x 256
#pragma unroll
    for (int i = 0; i < 8; i++) {
        int n = tid + i * 256;
        g_c[b * VOCAB + n] = 0.f;
        g_h[b * VOCAB + n] = 0.f;
        g_Hbf[0][b * VOCAB + n] = __float2bfloat16(0.f);
    }
    if (tid < LAT) out[(b * TSTEPS + 0) * LAT + tid] = 0.f;   // t=0 output exactly 0
}

// ---------------- helpers ----------------------------------------------------
__device__ __forceinline__ uint32_t smem_u32(const void* p) {
    return (uint32_t)__cvta_generic_to_shared(p);
}
__device__ __forceinline__ void cp_async16(uint32_t dst, const void* src) {
    asm volatile("cp.async.cg.shared.global [%0], [%1], 16;\n" :: "r"(dst), "l"(src));
}
__device__ __forceinline__ void ldsm_x4(uint32_t* r, uint32_t addr) {
    asm volatile("ldmatrix.sync.aligned.m8n8.x4.shared.b16 {%0,%1,%2,%3}, [%4];\n"
                 : "=r"(r[0]), "=r"(r[1]), "=r"(r[2]), "=r"(r[3]) : "r"(addr));
}
__device__ __forceinline__ void ldsm_x4_t(uint32_t* r, uint32_t addr) {
    asm volatile("ldmatrix.sync.aligned.m8n8.x4.trans.shared.b16 {%0,%1,%2,%3}, [%4];\n"
                 : "=r"(r[0]), "=r"(r[1]), "=r"(r[2]), "=r"(r[3]) : "r"(addr));
}
__device__ __forceinline__ void mma16816(float* d, const uint32_t* a, uint32_t b0, uint32_t b1) {
    asm volatile("mma.sync.aligned.m16n8k16.row.col.f32.bf16.bf16.f32 "
                 "{%0,%1,%2,%3}, {%4,%5,%6,%7}, {%8,%9}, {%0,%1,%2,%3};\n"
                 : "+f"(d[0]), "+f"(d[1]), "+f"(d[2]), "+f"(d[3])
                 : "r"(a[0]), "r"(a[1]), "r"(a[2]), "r"(a[3]), "r"(b0), "r"(b1));
}
__device__ __forceinline__ float fsig(float x)  { return __fdividef(1.f, 1.f + __expf(-x)); }
__device__ __forceinline__ float ftanh(float x) { return __fdividef(2.f, 1.f + __expf(-2.f * x)) - 1.f; }

// ---------------- fused GEMM + LSTM pointwise + softmax partials ------------
// Block j computes gate columns { j*16+q + g*2048 : q<16, g<4 } for all 32 rows.
// W smem tile col layout: col = g*16 + q.
__global__ __launch_bounds__(128, 1) void gemm_fused(const int* __restrict__ tokens,
                                                     const float* __restrict__ bias,
                                                     int t) {
    __shared__ __align__(16) __nv_bfloat16 As[STAGES][32 * APAD];
    __shared__ __align__(16) __nv_bfloat16 Ws[STAGES][KTILE * WPAD];
    __shared__ __align__(16) float gsm[32 * GPITCH];
    __shared__ float bsm[64];

    const int blk  = blockIdx.x;
    const int tid  = threadIdx.x;
    const int lane = tid & 31, warp = tid >> 5;
    const int mh = warp & 1;        // m offset 0/16
    const int nh = warp >> 1;       // smem-n half 0/32

    // stage bias chunk (64 values) into smem (no sync needed before mainloop's syncs)
    if (tid < 64) {
        int g = tid >> 4, q = tid & 15;
        bsm[tid] = bias[g * 2048 + blk * 16 + q];
    }

    // per-thread A-load source pointers
    const int am = tid >> 2, ac = tid & 3;                  // A row, 16B chunk
    const int v_am = tokens[am * TSTEPS + (t - 1)];         // token column t
    const __nv_bfloat16* a_emb = g_Ebf + (size_t)v_am * EMB;
    const __nv_bfloat16* a_h   = g_Hbf[(t - 1) & 1] + am * VOCAB;

    float acc[4][4];
#pragma unroll
    for (int i = 0; i < 4; i++)
#pragma unroll
        for (int jj = 0; jj < 4; jj++) acc[i][jj] = 0.f;

    auto issue_tile = [&](int st, int k0) {
        // A tile: emb rows for k<256, h rows after
        const __nv_bfloat16* src = (k0 < EMB) ? (a_emb + k0 + ac * 8)
                                              : (a_h + (k0 - EMB) + ac * 8);
        cp_async16(smem_u32(&As[st][am * APAD + ac * 8]), src);
        // W tile: 32 k-rows x 4 gate-chunks x 16 cols
#pragma unroll
        for (int j2 = 0; j2 < 2; j2++) {
            int idx = tid + j2 * 128;
            int k = idx >> 3, rem = idx & 7;
            int g = rem >> 1, half = rem & 1;
            cp_async16(smem_u32(&Ws[st][k * WPAD + g * 16 + half * 8]),
                       g_W + (size_t)(k0 + k) * NTOT + g * 2048 + blk * 16 + half * 8);
        }
    };

#pragma unroll
    for (int s = 0; s < STAGES - 1; ++s) {
        issue_tile(s, s * KTILE);
        asm volatile("cp.async.commit_group;\n");
    }

    for (int it = 0; it < NITER; ++it) {
        asm volatile("cp.async.wait_group %0;\n" :: "n"(STAGES - 2));
        __syncthreads();

        if (it + STAGES - 1 < NITER)
            issue_tile((it + STAGES - 1) & (STAGES - 1), (it + STAGES - 1) * KTILE);
        asm volatile("cp.async.commit_group;\n");

        const __nv_bfloat16* as = As[it & (STAGES - 1)];
        const __nv_bfloat16* ws = Ws[it & (STAGES - 1)];
#pragma unroll
        for (int ks = 0; ks < 2; ++ks) {
            uint32_t a[4];
            {
                int row = mh * 16 + (lane & 15);
                int col = ks * 16 + (lane >> 4) * 8;
                ldsm_x4(a, smem_u32(&as[row * APAD + col]));
            }
#pragma unroll
            for (int ns = 0; ns < 2; ++ns) {
                uint32_t bq[4];
                int krow = ks * 16 + (lane & 15);
                int col  = nh * 32 + ns * 16 + (lane >> 4) * 8;
                ldsm_x4_t(bq, smem_u32(&ws[krow * WPAD + col]));
                mma16816(acc[ns * 2 + 0], a, bq[0], bq[1]);
                mma16816(acc[ns * 2 + 1], a, bq[2], bq[3]);
            }
        }
    }
    __syncthreads();   // everyone done reading pipeline smem / ready for epilogue

    // stage accumulators -> gsm[row][col], col = g*16+q over [0,64)
#pragma unroll
    for (int nt = 0; nt < 4; ++nt) {
        int row = mh * 16 + (lane >> 2);
        int col = nh * 32 + nt * 8 + (lane & 3) * 2;
        *reinterpret_cast<float2*>(&gsm[row * GPITCH + col]) =
            make_float2(acc[nt][0], acc[nt][1]);
        *reinterpret_cast<float2*>(&gsm[(row + 8) * GPITCH + col]) =
            make_float2(acc[nt][2], acc[nt][3]);
    }
    __syncthreads();

    // LSTM pointwise + partial softmax sums. thread -> (row r, 4 q-values)
    {
        int r = tid >> 2, sub = tid & 3;
        int v = tokens[r * TSTEPS + (t - 1)];
        int s = tokens[r * TSTEPS + t];
        bool upd = (v != 0);
        __nv_bfloat16* hout = g_Hbf[t & 1] + r * VOCAB;

        float Z = 0.f, S = 0.f;
#pragma unroll
        for (int k = 0; k < 4; ++k) {
            int q = sub * 4 + k;
            int n = blk * 16 + q;
            float gi = gsm[r * GPITCH + q]      + bsm[q];
            float gf = gsm[r * GPITCH + 16 + q] + bsm[16 + q];
            float gg = gsm[r * GPITCH + 32 + q] + bsm[32 + q];
            float go = gsm[r * GPITCH + 48 + q] + bsm[48 + q];
            float ia = fsig(gi), fa = fsig(gf);
            float ga = ftanh(gg), oa = fsig(go);
            size_t ci = (size_t)r * VOCAB + n;
            float cn = fa * g_c[ci] + ia * ga;
            float hn = oa * ftanh(cn);
            float h;
            if (upd) { g_c[ci] = cn; h = hn; g_h[ci] = h; }
            else     { h = g_h[ci]; }
            hout[n] = __float2bfloat16(h);
            float e = __expf(h);                 // |h|<1: no max shift needed
            Z += e;
            S += (n < s) ? e : ((n == s) ? 0.5f * e : 0.f);
        }
        // reduce over the 4 lanes sharing this row (consecutive lanes, same warp)
        Z += __shfl_xor_sync(0xffffffffu, Z, 1);
        S += __shfl_xor_sync(0xffffffffu, S, 1);
        Z += __shfl_xor_sync(0xffffffffu, Z, 2);
        S += __shfl_xor_sync(0xffffffffu, S, 2);
        if (sub == 0) {
            g_partZ[r * NBLK + blk] = Z;
            g_partS[r * NBLK + blk] = S;
        }
    }
}

// ---------------- finalize: reduce partials, write z --------------------------
__global__ void finalize(float* __restrict__ out, int t) {
    int b = blockIdx.x, tid = threadIdx.x;     // 32 x 128
    int lane = tid & 31, wid = tid >> 5;
    __shared__ float rz[4], rs[4];
    float Z = g_partZ[b * NBLK + tid];
    float S = g_partS[b * NBLK + tid];
#pragma unroll
    for (int o = 16; o; o >>= 1) {
        Z += __shfl_xor_sync(0xffffffffu, Z, o);
        S += __shfl_xor_sync(0xffffffffu, S, o);
    }
    if (lane == 0) { rz[wid] = Z; rs[wid] = S; }
    __syncthreads();
    float Zt = rz[0] + rz[1] + rz[2] + rz[3];
    float St = rs[0] + rs[1] + rs[2] + rs[3];
    out[((size_t)b * TSTEPS + t) * LAT + tid] = 3.0f * St / Zt;
}

// ---------------- launch ----------------------------------------------------
extern "C" void kernel_launch(void* const* d_in, const int* in_sizes, int n_in,
                              void* d_out, int out_size) {
    const int* tokens = nullptr;
    const float *E = nullptr, *Wi = nullptr, *Wh = nullptr, *bias = nullptr;
    for (int i = 0; i < n_in; i++) {
        switch (in_sizes[i]) {
            case BATCH * TSTEPS:      tokens = (const int*)d_in[i];   break;
            case VOCAB * EMB:         E      = (const float*)d_in[i]; break;
            case EMB * 4 * VOCAB:     Wi     = (const float*)d_in[i]; break;
            case VOCAB * 4 * VOCAB:   Wh     = (const float*)d_in[i]; break;
            case 4 * VOCAB:           bias   = (const float*)d_in[i]; break;
        }
    }
    float* out = (float*)d_out;

    const int conv_blocks = ((KTOT * NTOT) + (VOCAB * EMB)) / 8 / 256;   // 9472
    convert_weights<<<conv_blocks, 256>>>(Wi, Wh, E);
    init_state<<<BATCH, 256>>>(out);

    for (int t = 1; t < TSTEPS; ++t) {
        gemm_fused<<<NBLK, 128>>>(tokens, bias, t);
        finalize<<<BATCH, 128>>>(out, t);
    }
}

// round 8
// speedup vs baseline: 1.5567x; 1.1279x over previous
#include <cuda_runtime.h>
#include <cuda_bf16.h>
#include <cstdint>
#include <cstddef>

#define VOCAB 2048
#define EMB 256
#define KTOT 2304          // EMB + VOCAB
#define NTOT 8192          // 4*VOCAB
#define BATCH 32
#define TSTEPS 8
#define LAT 128

#define NBLK 128           // persistent blocks; each owns 16 h-cols (x4 gates)
#define KTILE 64
#define NITER (KTOT / KTILE)   // 36
#define APITCH 72              // bf16 elems per A smem row (64 + 8 pad)
#define WPITCH 72              // bf16 elems per W smem row (64 + 8 pad)
#define GPITCH 66              // float pitch for gate staging (aliases As)

// ---------------- device scratch (no allocations allowed) -------------------
__device__ __align__(16) __nv_bfloat16 g_W[(size_t)KTOT * NTOT];   // 37.75 MB
__device__ __align__(16) __nv_bfloat16 g_Ebf[VOCAB * EMB];
__device__ __align__(16) __nv_bfloat16 g_Hbf[2][BATCH * VOCAB];    // ping-pong h
__device__ float g_c[BATCH * VOCAB];
__device__ float g_h[BATCH * VOCAB];
__device__ float g_partZ[2][BATCH * NBLK];                          // ping-pong
__device__ float g_partS[2][BATCH * NBLK];
__device__ unsigned g_bar_cnt = 0;     // monotonic ticket counter (never reset)

// ---------------- helpers ----------------------------------------------------
__device__ __forceinline__ uint32_t smem_u32(const void* p) {
    return (uint32_t)__cvta_generic_to_shared(p);
}
__device__ __forceinline__ void cp_async16(uint32_t dst, const void* src) {
    asm volatile("cp.async.cg.shared.global [%0], [%1], 16;\n" :: "r"(dst), "l"(src));
}
__device__ __forceinline__ void ldsm_x4(uint32_t* r, uint32_t addr) {
    asm volatile("ldmatrix.sync.aligned.m8n8.x4.shared.b16 {%0,%1,%2,%3}, [%4];\n"
                 : "=r"(r[0]), "=r"(r[1]), "=r"(r[2]), "=r"(r[3]) : "r"(addr));
}
__device__ __forceinline__ void ldsm_x4_t(uint32_t* r, uint32_t addr) {
    asm volatile("ldmatrix.sync.aligned.m8n8.x4.trans.shared.b16 {%0,%1,%2,%3}, [%4];\n"
                 : "=r"(r[0]), "=r"(r[1]), "=r"(r[2]), "=r"(r[3]) : "r"(addr));
}
__device__ __forceinline__ void mma16816(float* d, const uint32_t* a, uint32_t b0, uint32_t b1) {
    asm volatile("mma.sync.aligned.m16n8k16.row.col.f32.bf16.bf16.f32 "
                 "{%0,%1,%2,%3}, {%4,%5,%6,%7}, {%8,%9}, {%0,%1,%2,%3};\n"
                 : "+f"(d[0]), "+f"(d[1]), "+f"(d[2]), "+f"(d[3])
                 : "r"(a[0]), "r"(a[1]), "r"(a[2]), "r"(a[3]), "r"(b0), "r"(b1));
}
__device__ __forceinline__ float fsig(float x)  { return __fdividef(1.f, 1.f + __expf(-x)); }
__device__ __forceinline__ float ftanh(float x) { return __fdividef(2.f, 1.f + __expf(-2.f * x)) - 1.f; }

__device__ __forceinline__ void cvt8(const float* __restrict__ src,
                                     __nv_bfloat16* __restrict__ dst) {
    float4 f0 = reinterpret_cast<const float4*>(src)[0];
    float4 f1 = reinterpret_cast<const float4*>(src)[1];
    __nv_bfloat162 b0 = __float22bfloat162_rn(make_float2(f0.x, f0.y));
    __nv_bfloat162 b1 = __float22bfloat162_rn(make_float2(f0.z, f0.w));
    __nv_bfloat162 b2 = __float22bfloat162_rn(make_float2(f1.x, f1.y));
    __nv_bfloat162 b3 = __float22bfloat162_rn(make_float2(f1.z, f1.w));
    uint4 pv;
    pv.x = *reinterpret_cast<unsigned*>(&b0);
    pv.y = *reinterpret_cast<unsigned*>(&b1);
    pv.z = *reinterpret_cast<unsigned*>(&b2);
    pv.w = *reinterpret_cast<unsigned*>(&b3);
    *reinterpret_cast<uint4*>(dst) = pv;
}

// Reset-free monotonic grid barrier. All observations go through L2 atomics
// (no plain loads -> no stale-L1 hazard), no reset store to race. A block's
// fresh read of cnt before its own arrival is provably < its target, so the
// early-fall-through failure mode of the generation barrier cannot occur.
// NBLK (128) <= 148 SMs at 1 CTA/SM -> all blocks co-resident.
__device__ __forceinline__ void grid_sync() {
    __syncthreads();
    if (threadIdx.x == 0) {
        __threadfence();                               // release prior stores
        unsigned ticket = atomicAdd(&g_bar_cnt, 1u);
        unsigned target = ticket - (ticket % NBLK) + NBLK;
        while (atomicAdd(&g_bar_cnt, 0u) < target) __nanosleep(64);
        __threadfence();                               // acquire others' stores
    }
    __syncthreads();
}

// ---------------- the one persistent kernel ---------------------------------
__global__ __launch_bounds__(256, 1) void persistent_kernel(
    const int* __restrict__ tokens, const float* __restrict__ E,
    const float* __restrict__ Wi, const float* __restrict__ Wh,
    const float* __restrict__ bias, float* __restrict__ out)
{
    __shared__ __align__(16) __nv_bfloat16 As[3][32 * APITCH];   // 13.8 KB (aliased by gsm)
    __shared__ __align__(16) __nv_bfloat16 Ws[3][KTILE * WPITCH];// 27.6 KB
    __shared__ float bsm[64];
    __shared__ float redz[8], reds[8];
    float* gsm = reinterpret_cast<float*>(&As[0][0]);            // 32*GPITCH floats

    const int blk  = blockIdx.x;
    const int tid  = threadIdx.x;
    const int lane = tid & 31, warp = tid >> 5;
    const int mh = warp & 1;        // m half: rows mh*16..+16
    const int nq = warp >> 1;       // n quarter: smem cols nq*16..+16

    // ---------- phase 0: convert weights + embeddings to bf16 ----------
    {
        const size_t NW = (size_t)KTOT * NTOT;        // 18,874,368
        const size_t NI = (size_t)EMB * NTOT;         // 2,097,152
        // total chunks = (NW + VOCAB*EMB)/8 = 2,424,832 = NBLK * 256 * 74
        for (int i = 0; i < 74; i++) {
            size_t idx = (((size_t)blk * 74 + i) * 256 + tid) * 8;
            if (idx < NW) {
                const float* src = (idx < NI) ? (Wi + idx) : (Wh + (idx - NI));
                cvt8(src, g_W + idx);
            } else {
                size_t e = idx - NW;
                cvt8(E + e, g_Ebf + e);
            }
        }
    }
    // ---------- init state: block owns cols [blk*16, blk*16+16) of c/h ------
    {
#pragma unroll
        for (int i = 0; i < 2; i++) {
            int e = tid + i * 256;                    // 0..511
            int r = e >> 4, q = e & 15;
            size_t ci = (size_t)r * VOCAB + blk * 16 + q;
            g_c[ci] = 0.f;
            g_h[ci] = 0.f;
        }
#pragma unroll
        for (int i = 0; i < 2; i++) {                 // zero Hbf[0] slice
            int e = blk * 512 + tid + i * 256;
            g_Hbf[0][e] = __float2bfloat16(0.f);
        }
        if (blk < 32 && tid < LAT)
            out[((size_t)blk * TSTEPS + 0) * LAT + tid] = 0.f;   // t=0 output
        if (tid < 64)
            bsm[tid] = bias[(tid >> 4) * 2048 + blk * 16 + (tid & 15)];
    }
    grid_sync();

    // ---------- step loop ----------
    for (int t = 1; t < TSTEPS; ++t) {
        // A-load mapping: row am (batch), chunk ac (8 elems each), 64-col tiles
        const int am = tid >> 3, ac = tid & 7;
        const int v_am = __ldg(&tokens[am * TSTEPS + (t - 1)]);
        const __nv_bfloat16* a_emb = g_Ebf + (size_t)v_am * EMB;
        const __nv_bfloat16* a_h   = g_Hbf[(t - 1) & 1] + am * VOCAB;

        float acc[2][4];
#pragma unroll
        for (int i = 0; i < 2; i++)
#pragma unroll
            for (int j = 0; j < 4; j++) acc[i][j] = 0.f;

        auto issue_tile = [&](int st, int k0) {
            // A tile: 32 rows x 64 k-elems; first 4 tiles from emb, rest from h
            const __nv_bfloat16* src = (k0 < EMB) ? (a_emb + k0 + ac * 8)
                                                  : (a_h + (k0 - EMB) + ac * 8);
            cp_async16(smem_u32(&As[st][am * APITCH + ac * 8]), src);
            // W tile: 64 k-rows x 64 cols (col = g*16+q), 512 chunks -> 2/thread
#pragma unroll
            for (int j2 = 0; j2 < 2; j2++) {
                int idx = tid + j2 * 256;
                int k = idx >> 3, rem = idx & 7;
                int g = rem >> 1, half = rem & 1;
                cp_async16(smem_u32(&Ws[st][k * WPITCH + g * 16 + half * 8]),
                           g_W + (size_t)(k0 + k) * NTOT + g * 2048 + blk * 16 + half * 8);
            }
        };

#pragma unroll
        for (int s = 0; s < 2; ++s) {
            issue_tile(s, s * KTILE);
            asm volatile("cp.async.commit_group;\n");
        }

        for (int it = 0; it < NITER; ++it) {
            asm volatile("cp.async.wait_group 1;\n");
            __syncthreads();

            if (it + 2 < NITER) {
                int st = (it + 2) % 3;
                issue_tile(st, (it + 2) * KTILE);
            }
            asm volatile("cp.async.commit_group;\n");

            const __nv_bfloat16* as = As[it % 3];
            const __nv_bfloat16* ws = Ws[it % 3];
#pragma unroll
            for (int ks = 0; ks < 4; ++ks) {
                uint32_t a[4];
                {
                    int row = mh * 16 + (lane & 15);
                    int col = ks * 16 + (lane >> 4) * 8;
                    ldsm_x4(a, smem_u32(&as[row * APITCH + col]));
                }
                uint32_t bq[4];
                {
                    int krow = ks * 16 + (lane & 15);
                    int col  = nq * 16 + (lane >> 4) * 8;
                    ldsm_x4_t(bq, smem_u32(&ws[krow * WPITCH + col]));
                }
                mma16816(acc[0], a, bq[0], bq[1]);
                mma16816(acc[1], a, bq[2], bq[3]);
            }
            __syncthreads();   // protect As/Ws stage reuse (and gsm alias later)
        }

        // ---------- epilogue: stage accs -> gsm, LSTM pointwise, partials ----
#pragma unroll
        for (int ns = 0; ns < 2; ++ns) {
            int row = mh * 16 + (lane >> 2);
            int col = nq * 16 + ns * 8 + (lane & 3) * 2;
            *reinterpret_cast<float2*>(&gsm[row * GPITCH + col]) =
                make_float2(acc[ns][0], acc[ns][1]);
            *reinterpret_cast<float2*>(&gsm[(row + 8) * GPITCH + col]) =
                make_float2(acc[ns][2], acc[ns][3]);
        }
        __syncthreads();

        {
            int r = tid >> 3, sub = tid & 7;      // row, 2 q-values per thread
            int v = __ldg(&tokens[r * TSTEPS + (t - 1)]);
            int s = __ldg(&tokens[r * TSTEPS + t]);
            bool upd = (v != 0);
            __nv_bfloat16* hout = g_Hbf[t & 1] + r * VOCAB;

            float Z = 0.f, S = 0.f;
#pragma unroll
            for (int k = 0; k < 2; ++k) {
                int q = sub * 2 + k;
                int n = blk * 16 + q;
                float gi = gsm[r * GPITCH + q]      + bsm[q];
                float gf = gsm[r * GPITCH + 16 + q] + bsm[16 + q];
                float gg = gsm[r * GPITCH + 32 + q] + bsm[32 + q];
                float go = gsm[r * GPITCH + 48 + q] + bsm[48 + q];
                float ia = fsig(gi), fa = fsig(gf);
                float ga = ftanh(gg), oa = fsig(go);
                size_t ci = (size_t)r * VOCAB + n;
                float cn = fa * g_c[ci] + ia * ga;
                float hn = oa * ftanh(cn);
                float h;
                if (upd) { g_c[ci] = cn; h = hn; g_h[ci] = h; }
                else     { h = g_h[ci]; }
                hout[n] = __float2bfloat16(h);
                float e = __expf(h);               // |h|<1: no max shift needed
                Z += e;
                S += (n < s) ? e : ((n == s) ? 0.5f * e : 0.f);
            }
            // reduce the 8 lanes sharing this row (consecutive, same warp)
#pragma unroll
            for (int o = 1; o < 8; o <<= 1) {
                Z += __shfl_xor_sync(0xffffffffu, Z, o);
                S += __shfl_xor_sync(0xffffffffu, S, o);
            }
            if (sub == 0) {
                g_partZ[t & 1][r * NBLK + blk] = Z;
                g_partS[t & 1][r * NBLK + blk] = S;
            }
        }

        grid_sync();   // h + partials visible everywhere

        // ---------- finalize (blocks 0..31) while others start next GEMM ----
        if (blk < 32) {
            float Z = 0.f, S = 0.f;
            if (tid < NBLK) {
                Z = g_partZ[t & 1][blk * NBLK + tid];
                S = g_partS[t & 1][blk * NBLK + tid];
            }
#pragma unroll
            for (int o = 16; o; o >>= 1) {
                Z += __shfl_xor_sync(0xffffffffu, Z, o);
                S += __shfl_xor_sync(0xffffffffu, S, o);
            }
            if (lane == 0) { redz[warp] = Z; reds[warp] = S; }
            __syncthreads();
            float Zt = redz[0] + redz[1] + redz[2] + redz[3];
            float St = reds[0] + reds[1] + reds[2] + reds[3];
            if (tid < LAT)
                out[((size_t)blk * TSTEPS + t) * LAT + tid] = 3.0f * St / Zt;
            __syncthreads();   // redz reuse safety for next t
        }
        // no second barrier: next step's partials/h use the other ping-pong slot,
        // and c/h fp32 state is block-private.
    }
}

// ---------------- launch ----------------------------------------------------
extern "C" void kernel_launch(void* const* d_in, const int* in_sizes, int n_in,
                              void* d_out, int out_size) {
    const int* tokens = nullptr;
    const float *E = nullptr, *Wi = nullptr, *Wh = nullptr, *bias = nullptr;
    for (int i = 0; i < n_in; i++) {
        switch (in_sizes[i]) {
            case BATCH * TSTEPS:      tokens = (const int*)d_in[i];   break;
            case VOCAB * EMB:         E      = (const float*)d_in[i]; break;
            case EMB * 4 * VOCAB:     Wi     = (const float*)d_in[i]; break;
            case VOCAB * 4 * VOCAB:   Wh     = (const float*)d_in[i]; break;
            case 4 * VOCAB:           bias   = (const float*)d_in[i]; break;
        }
    }
    float* out = (float*)d_out;
    persistent_kernel<<<NBLK, 256>>>(tokens, E, Wi, Wh, bias, out);
}

// round 9
// speedup vs baseline: 1.6082x; 1.0330x over previous
#include <cuda_runtime.h>
#include <cuda_bf16.h>
#include <cstdint>
#include <cstddef>

#define VOCAB 2048
#define EMB 256
#define KTOT 2304          // EMB + VOCAB
#define NTOT 8192          // 4*VOCAB
#define BATCH 32
#define TSTEPS 8
#define LAT 128

#define NBLK 128           // persistent blocks; each owns 16 h-cols (x4 gates)
#define THREADS 512        // 16 warps: mh(2) x nq(4) x kg(2)
#define KTILE 64
#define NITER (KTOT / KTILE)   // 36
#define NITER1 (EMB / KTILE)   // 4  (t==1: h==0, only emb rows matter)
#define APITCH 72              // bf16 elems per A smem row (64 + 8 pad)
#define WPITCH 72              // bf16 elems per W smem row (64 + 8 pad)
#define GPITCH 66              // float pitch for gate staging (aliases As)

// ---------------- device scratch (no allocations allowed) -------------------
__device__ __align__(16) __nv_bfloat16 g_W[(size_t)KTOT * NTOT];   // 37.75 MB
__device__ __align__(16) __nv_bfloat16 g_Ebf[VOCAB * EMB];
__device__ __align__(16) __nv_bfloat16 g_Hbf[2][BATCH * VOCAB];    // ping-pong h
__device__ float g_c[BATCH * VOCAB];
__device__ float g_h[BATCH * VOCAB];
__device__ float g_partZ[2][BATCH * NBLK];                          // ping-pong
__device__ float g_partS[2][BATCH * NBLK];
__device__ unsigned g_bar_cnt = 0;     // monotonic ticket counter (never reset)

// ---------------- helpers ----------------------------------------------------
__device__ __forceinline__ uint32_t smem_u32(const void* p) {
    return (uint32_t)__cvta_generic_to_shared(p);
}
__device__ __forceinline__ void cp_async16(uint32_t dst, const void* src) {
    asm volatile("cp.async.cg.shared.global [%0], [%1], 16;\n" :: "r"(dst), "l"(src));
}
__device__ __forceinline__ void ldsm_x4(uint32_t* r, uint32_t addr) {
    asm volatile("ldmatrix.sync.aligned.m8n8.x4.shared.b16 {%0,%1,%2,%3}, [%4];\n"
                 : "=r"(r[0]), "=r"(r[1]), "=r"(r[2]), "=r"(r[3]) : "r"(addr));
}
__device__ __forceinline__ void ldsm_x4_t(uint32_t* r, uint32_t addr) {
    asm volatile("ldmatrix.sync.aligned.m8n8.x4.trans.shared.b16 {%0,%1,%2,%3}, [%4];\n"
                 : "=r"(r[0]), "=r"(r[1]), "=r"(r[2]), "=r"(r[3]) : "r"(addr));
}
__device__ __forceinline__ void mma16816(float* d, const uint32_t* a, uint32_t b0, uint32_t b1) {
    asm volatile("mma.sync.aligned.m16n8k16.row.col.f32.bf16.bf16.f32 "
                 "{%0,%1,%2,%3}, {%4,%5,%6,%7}, {%8,%9}, {%0,%1,%2,%3};\n"
                 : "+f"(d[0]), "+f"(d[1]), "+f"(d[2]), "+f"(d[3])
                 : "r"(a[0]), "r"(a[1]), "r"(a[2]), "r"(a[3]), "r"(b0), "r"(b1));
}
__device__ __forceinline__ float fsig(float x)  { return __fdividef(1.f, 1.f + __expf(-x)); }
__device__ __forceinline__ float ftanh(float x) { return __fdividef(2.f, 1.f + __expf(-2.f * x)) - 1.f; }

__device__ __forceinline__ void cvt8(const float* __restrict__ src,
                                     __nv_bfloat16* __restrict__ dst) {
    float4 f0 = reinterpret_cast<const float4*>(src)[0];
    float4 f1 = reinterpret_cast<const float4*>(src)[1];
    __nv_bfloat162 b0 = __float22bfloat162_rn(make_float2(f0.x, f0.y));
    __nv_bfloat162 b1 = __float22bfloat162_rn(make_float2(f0.z, f0.w));
    __nv_bfloat162 b2 = __float22bfloat162_rn(make_float2(f1.x, f1.y));
    __nv_bfloat162 b3 = __float22bfloat162_rn(make_float2(f1.z, f1.w));
    uint4 pv;
    pv.x = *reinterpret_cast<unsigned*>(&b0);
    pv.y = *reinterpret_cast<unsigned*>(&b1);
    pv.z = *reinterpret_cast<unsigned*>(&b2);
    pv.w = *reinterpret_cast<unsigned*>(&b3);
    *reinterpret_cast<uint4*>(dst) = pv;
}

// Reset-free monotonic grid barrier (L2 atomics only; proven in R8).
__device__ __forceinline__ void grid_sync() {
    __syncthreads();
    if (threadIdx.x == 0) {
        __threadfence();                               // release prior stores
        unsigned ticket = atomicAdd(&g_bar_cnt, 1u);
        unsigned target = ticket - (ticket % NBLK) + NBLK;
        while (atomicAdd(&g_bar_cnt, 0u) < target) __nanosleep(64);
        __threadfence();                               // acquire others' stores
    }
    __syncthreads();
}

// ---------------- the one persistent kernel ---------------------------------
__global__ __launch_bounds__(THREADS, 1) void persistent_kernel(
    const int* __restrict__ tokens, const float* __restrict__ E,
    const float* __restrict__ Wi, const float* __restrict__ Wh,
    const float* __restrict__ bias, float* __restrict__ out)
{
    __shared__ __align__(16) __nv_bfloat16 As[3][32 * APITCH];   // 13.8 KB (aliased by gsm)
    __shared__ __align__(16) __nv_bfloat16 Ws[3][KTILE * WPITCH];// 27.6 KB
    __shared__ float bsm[64];
    __shared__ float redz[4], reds[4];
    float* gsm = reinterpret_cast<float*>(&As[0][0]);            // 32*GPITCH floats

    const int blk  = blockIdx.x;
    const int tid  = threadIdx.x;
    const int lane = tid & 31, warp = tid >> 5;      // 16 warps
    const int mh = warp & 1;          // m half: rows mh*16..+16
    const int nq = (warp >> 1) & 3;   // n quarter: smem cols nq*16..+16
    const int kg = warp >> 3;         // k-group: ks chunks kg*2 + {0,1}

    // ---------- phase 0: convert weights + embeddings to bf16 ----------
    {
        const size_t NW = (size_t)KTOT * NTOT;        // 18,874,368
        const size_t NI = (size_t)EMB * NTOT;         // 2,097,152
        // chunks = (NW + VOCAB*EMB)/8 = 2,424,832 = 128 * 512 * 37
        for (int i = 0; i < 37; i++) {
            size_t idx = ((size_t)i * (NBLK * THREADS) + blk * THREADS + tid) * 8;
            if (idx < NW) {
                const float* src = (idx < NI) ? (Wi + idx) : (Wh + (idx - NI));
                cvt8(src, g_W + idx);
            } else {
                size_t e = idx - NW;
                cvt8(E + e, g_Ebf + e);
            }
        }
    }
    // ---------- init state: block owns cols [blk*16, blk*16+16) of c/h ------
    {
        {   // 512 entries, one per thread
            int r = tid >> 4, q = tid & 15;
            size_t ci = (size_t)r * VOCAB + blk * 16 + q;
            g_c[ci] = 0.f;
            g_h[ci] = 0.f;
        }
        g_Hbf[0][blk * THREADS + tid] = __float2bfloat16(0.f);   // 512/block
        if (blk < 32 && tid < LAT)
            out[((size_t)blk * TSTEPS + 0) * LAT + tid] = 0.f;   // t=0 output
        if (tid < 64)
            bsm[tid] = bias[(tid >> 4) * 2048 + blk * 16 + (tid & 15)];
    }
    grid_sync();

    // ---------- step loop ----------
    for (int t = 1; t < TSTEPS; ++t) {
        const int nit = (t == 1) ? NITER1 : NITER;   // t=1: h==0 -> emb rows only

        // A-load mapping (threads 0..255): row am, 8-elem chunk ac
        const int am = tid >> 3, ac = tid & 7;
        const int v_am = __ldg(&tokens[(am & 31) * TSTEPS + (t - 1)]);
        const __nv_bfloat16* a_emb = g_Ebf + (size_t)v_am * EMB;
        const __nv_bfloat16* a_h   = g_Hbf[(t - 1) & 1] + (am & 31) * VOCAB;

        float acc[2][4];
#pragma unroll
        for (int i = 0; i < 2; i++)
#pragma unroll
            for (int j = 0; j < 4; j++) acc[i][j] = 0.f;

        auto issue_tile = [&](int st, int k0) {
            // A tile: 32 rows x 64 k (256 chunks; threads < 256)
            if (tid < 256) {
                const __nv_bfloat16* src = (k0 < EMB) ? (a_emb + k0 + ac * 8)
                                                      : (a_h + (k0 - EMB) + ac * 8);
                cp_async16(smem_u32(&As[st][am * APITCH + ac * 8]), src);
            }
            // W tile: 64 k-rows x 64 cols (col = g*16+q): 512 chunks, 1/thread
            {
                int k = tid >> 3, rem = tid & 7;
                int g = rem >> 1, half = rem & 1;
                cp_async16(smem_u32(&Ws[st][k * WPITCH + g * 16 + half * 8]),
                           g_W + (size_t)(k0 + k) * NTOT + g * 2048 + blk * 16 + half * 8);
            }
        };

#pragma unroll
        for (int s = 0; s < 2; ++s) {
            issue_tile(s, s * KTILE);
            asm volatile("cp.async.commit_group;\n");
        }

        for (int it = 0; it < nit; ++it) {
            asm volatile("cp.async.wait_group 1;\n");
            __syncthreads();    // all warps done with iter it-1; tile it ready

            if (it + 2 < nit)
                issue_tile((it + 2) % 3, (it + 2) * KTILE);
            asm volatile("cp.async.commit_group;\n");

            const __nv_bfloat16* as = As[it % 3];
            const __nv_bfloat16* ws = Ws[it % 3];
#pragma unroll
            for (int k2 = 0; k2 < 2; ++k2) {
                const int ks = kg * 2 + k2;
                uint32_t a[4];
                {
                    int row = mh * 16 + (lane & 15);
                    int col = ks * 16 + (lane >> 4) * 8;
                    ldsm_x4(a, smem_u32(&as[row * APITCH + col]));
                }
                uint32_t bq[4];
                {
                    int krow = ks * 16 + (lane & 15);
                    int col  = nq * 16 + (lane >> 4) * 8;
                    ldsm_x4_t(bq, smem_u32(&ws[krow * WPITCH + col]));
                }
                mma16816(acc[0], a, bq[0], bq[1]);
                mma16816(acc[1], a, bq[2], bq[3]);
            }
            // no trailing sync: next iteration's top sync protects buffer reuse
        }
        __syncthreads();        // last iteration's reads done before gsm alias

        // ---------- epilogue: 2-phase acc merge (kg split) -> gsm ----------
#pragma unroll
        for (int ns = 0; ns < 2; ++ns) {
            int row = mh * 16 + (lane >> 2);
            int col = nq * 16 + ns * 8 + (lane & 3) * 2;
            if (kg == 0) {
                *reinterpret_cast<float2*>(&gsm[row * GPITCH + col]) =
                    make_float2(acc[ns][0], acc[ns][1]);
                *reinterpret_cast<float2*>(&gsm[(row + 8) * GPITCH + col]) =
                    make_float2(acc[ns][2], acc[ns][3]);
            }
        }
        __syncthreads();
#pragma unroll
        for (int ns = 0; ns < 2; ++ns) {
            int row = mh * 16 + (lane >> 2);
            int col = nq * 16 + ns * 8 + (lane & 3) * 2;
            if (kg == 1) {
                float2* p0 = reinterpret_cast<float2*>(&gsm[row * GPITCH + col]);
                float2 v0 = *p0; v0.x += acc[ns][0]; v0.y += acc[ns][1]; *p0 = v0;
                float2* p1 = reinterpret_cast<float2*>(&gsm[(row + 8) * GPITCH + col]);
                float2 v1 = *p1; v1.x += acc[ns][2]; v1.y += acc[ns][3]; *p1 = v1;
            }
        }
        __syncthreads();

        // ---------- LSTM pointwise + partial sums: 1 (row,q) per thread ------
        {
            int r = tid >> 4, q = tid & 15;
            int v = __ldg(&tokens[r * TSTEPS + (t - 1)]);
            int s = __ldg(&tokens[r * TSTEPS + t]);
            bool upd = (v != 0);
            int n = blk * 16 + q;

            float gi = gsm[r * GPITCH + q]      + bsm[q];
            float gf = gsm[r * GPITCH + 16 + q] + bsm[16 + q];
            float gg = gsm[r * GPITCH + 32 + q] + bsm[32 + q];
            float go = gsm[r * GPITCH + 48 + q] + bsm[48 + q];
            float ia = fsig(gi), fa = fsig(gf);
            float ga = ftanh(gg), oa = fsig(go);
            size_t ci = (size_t)r * VOCAB + n;
            float cn = fa * g_c[ci] + ia * ga;
            float hn = oa * ftanh(cn);
            float h;
            if (upd) { g_c[ci] = cn; h = hn; g_h[ci] = h; }
            else     { h = g_h[ci]; }
            g_Hbf[t & 1][r * VOCAB + n] = __float2bfloat16(h);
            float e = __expf(h);               // |h|<1: no max shift needed
            float Z = e;
            float S = (n < s) ? e : ((n == s) ? 0.5f * e : 0.f);
            // reduce over the 16 lanes sharing a row (half-warp, xor-safe)
#pragma unroll
            for (int o = 1; o < 16; o <<= 1) {
                Z += __shfl_xor_sync(0xffffffffu, Z, o);
                S += __shfl_xor_sync(0xffffffffu, S, o);
            }
            if (q == 0) {
                g_partZ[t & 1][r * NBLK + blk] = Z;
                g_partS[t & 1][r * NBLK + blk] = S;
            }
        }

        grid_sync();   // h + partials visible everywhere

        // ---------- finalize (blocks 0..31) while others start next GEMM ----
        if (blk < 32) {
            if (tid < NBLK) {      // warps 0..3 (full warps)
                float Z = g_partZ[t & 1][blk * NBLK + tid];
                float S = g_partS[t & 1][blk * NBLK + tid];
#pragma unroll
                for (int o = 16; o; o >>= 1) {
                    Z += __shfl_xor_sync(0xffffffffu, Z, o);
                    S += __shfl_xor_sync(0xffffffffu, S, o);
                }
                if (lane == 0) { redz[warp] = Z; reds[warp] = S; }
            }
            __syncthreads();
            float Zt = redz[0] + redz[1] + redz[2] + redz[3];
            float St = reds[0] + reds[1] + reds[2] + reds[3];
            if (tid < LAT)
                out[((size_t)blk * TSTEPS + t) * LAT + tid] = 3.0f * St / Zt;
            __syncthreads();   // redz reuse safety for next t
        }
        // no second barrier: next step uses the other ping-pong slot; c/h is
        // block-private.
    }
}

// ---------------- launch ----------------------------------------------------
extern "C" void kernel_launch(void* const* d_in, const int* in_sizes, int n_in,
                              void* d_out, int out_size) {
    const int* tokens = nullptr;
    const float *E = nullptr, *Wi = nullptr, *Wh = nullptr, *bias = nullptr;
    for (int i = 0; i < n_in; i++) {
        switch (in_sizes[i]) {
            case BATCH * TSTEPS:      tokens = (const int*)d_in[i];   break;
            case VOCAB * EMB:         E      = (const float*)d_in[i]; break;
            case EMB * 4 * VOCAB:     Wi     = (const float*)d_in[i]; break;
            case VOCAB * 4 * VOCAB:   Wh     = (const float*)d_in[i]; break;
            case 4 * VOCAB:           bias   = (const float*)d_in[i]; break;
        }
    }
    float* out = (float*)d_out;
    persistent_kernel<<<NBLK, THREADS>>>(tokens, E, Wi, Wh, bias, out);
}

// round 10
// speedup vs baseline: 1.8605x; 1.1569x over previous
#include <cuda_runtime.h>
#include <cuda_bf16.h>
#include <cstdint>
#include <cstddef>

#define VOCAB 2048
#define EMB 256
#define KTOT 2304          // EMB + VOCAB
#define NTOT 8192          // 4*VOCAB
#define BATCH 32
#define TSTEPS 8
#define LAT 128

#define NBLK 128           // persistent blocks; each owns 16 h-cols (x4 gates)
#define THREADS 512        // 16 warps: mh(2) x nq(4) x kg(2)
#define KTILE 128
#define NITER (KTOT / KTILE)   // 18
#define NITER1 (EMB / KTILE)   // 2  (t==1: h==0, only emb rows matter)
#define STAGES 4
#define APITCH 136             // bf16 elems per A smem row (128 + 8 pad)
#define WPITCH 72              // bf16 elems per W smem row (64 + 8 pad)
#define GPITCH 66              // float pitch for gate staging (aliases As[0])
#define ASTAGE (32 * APITCH)       // 4352 elems
#define WSTAGE (KTILE * WPITCH)    // 9216 elems
#define SMEM_BYTES ((STAGES * ASTAGE + STAGES * WSTAGE) * 2)   // 108,544 B

// ---------------- device scratch (no allocations allowed) -------------------
__device__ __align__(16) __nv_bfloat16 g_W[(size_t)KTOT * NTOT];   // 37.75 MB
__device__ __align__(16) __nv_bfloat16 g_Ebf[VOCAB * EMB];
__device__ __align__(16) __nv_bfloat16 g_Hbf[2][BATCH * VOCAB];    // ping-pong h
__device__ float g_c[BATCH * VOCAB];
__device__ float g_h[BATCH * VOCAB];
__device__ float g_partZ[2][BATCH * NBLK];                          // ping-pong
__device__ float g_partS[2][BATCH * NBLK];
__device__ unsigned g_bar_cnt = 0;     // monotonic ticket counter (never reset)

// ---------------- helpers ----------------------------------------------------
__device__ __forceinline__ uint32_t smem_u32(const void* p) {
    return (uint32_t)__cvta_generic_to_shared(p);
}
__device__ __forceinline__ void cp_async16(uint32_t dst, const void* src) {
    asm volatile("cp.async.cg.shared.global [%0], [%1], 16;\n" :: "r"(dst), "l"(src));
}
__device__ __forceinline__ void ldsm_x4(uint32_t* r, uint32_t addr) {
    asm volatile("ldmatrix.sync.aligned.m8n8.x4.shared.b16 {%0,%1,%2,%3}, [%4];\n"
                 : "=r"(r[0]), "=r"(r[1]), "=r"(r[2]), "=r"(r[3]) : "r"(addr));
}
__device__ __forceinline__ void ldsm_x4_t(uint32_t* r, uint32_t addr) {
    asm volatile("ldmatrix.sync.aligned.m8n8.x4.trans.shared.b16 {%0,%1,%2,%3}, [%4];\n"
                 : "=r"(r[0]), "=r"(r[1]), "=r"(r[2]), "=r"(r[3]) : "r"(addr));
}
__device__ __forceinline__ void mma16816(float* d, const uint32_t* a, uint32_t b0, uint32_t b1) {
    asm volatile("mma.sync.aligned.m16n8k16.row.col.f32.bf16.bf16.f32 "
                 "{%0,%1,%2,%3}, {%4,%5,%6,%7}, {%8,%9}, {%0,%1,%2,%3};\n"
                 : "+f"(d[0]), "+f"(d[1]), "+f"(d[2]), "+f"(d[3])
                 : "r"(a[0]), "r"(a[1]), "r"(a[2]), "r"(a[3]), "r"(b0), "r"(b1));
}
__device__ __forceinline__ float fsig(float x)  { return __fdividef(1.f, 1.f + __expf(-x)); }
__device__ __forceinline__ float ftanh(float x) { return __fdividef(2.f, 1.f + __expf(-2.f * x)) - 1.f; }

__device__ __forceinline__ void cvt8(const float* __restrict__ src,
                                     __nv_bfloat16* __restrict__ dst) {
    float4 f0 = reinterpret_cast<const float4*>(src)[0];
    float4 f1 = reinterpret_cast<const float4*>(src)[1];
    __nv_bfloat162 b0 = __float22bfloat162_rn(make_float2(f0.x, f0.y));
    __nv_bfloat162 b1 = __float22bfloat162_rn(make_float2(f0.z, f0.w));
    __nv_bfloat162 b2 = __float22bfloat162_rn(make_float2(f1.x, f1.y));
    __nv_bfloat162 b3 = __float22bfloat162_rn(make_float2(f1.z, f1.w));
    uint4 pv;
    pv.x = *reinterpret_cast<unsigned*>(&b0);
    pv.y = *reinterpret_cast<unsigned*>(&b1);
    pv.z = *reinterpret_cast<unsigned*>(&b2);
    pv.w = *reinterpret_cast<unsigned*>(&b3);
    *reinterpret_cast<uint4*>(dst) = pv;
}

// Reset-free monotonic grid barrier (L2 atomics only; proven in R8).
__device__ __forceinline__ void grid_sync() {
    __syncthreads();
    if (threadIdx.x == 0) {
        __threadfence();                               // release prior stores
        unsigned ticket = atomicAdd(&g_bar_cnt, 1u);
        unsigned target = ticket - (ticket % NBLK) + NBLK;
        while (atomicAdd(&g_bar_cnt, 0u) < target) __nanosleep(64);
        __threadfence();                               // acquire others' stores
    }
    __syncthreads();
}

// ---------------- the one persistent kernel ---------------------------------
__global__ __launch_bounds__(THREADS, 1) void persistent_kernel(
    const int* __restrict__ tokens, const float* __restrict__ E,
    const float* __restrict__ Wi, const float* __restrict__ Wh,
    const float* __restrict__ bias, float* __restrict__ out)
{
    extern __shared__ __align__(16) char dynsmem[];
    __nv_bfloat16* Asm = reinterpret_cast<__nv_bfloat16*>(dynsmem);          // STAGES*ASTAGE
    __nv_bfloat16* Wsm = Asm + STAGES * ASTAGE;                               // STAGES*WSTAGE
    float* gsm = reinterpret_cast<float*>(Asm);        // 32*GPITCH floats = 8448B < ASTAGE*2
    __shared__ float bsm[64];
    __shared__ float redz[4], reds[4];

    const int blk  = blockIdx.x;
    const int tid  = threadIdx.x;
    const int lane = tid & 31, warp = tid >> 5;      // 16 warps
    const int mh = warp & 1;          // m half: rows mh*16..+16
    const int nq = (warp >> 1) & 3;   // n quarter: smem cols nq*16..+16
    const int kg = warp >> 3;         // k-group: ks chunks kg*4 + {0..3}

    // ---------- phase 0: convert weights + embeddings to bf16 ----------
    // chunk counts divide the grid exactly: Wi = 4 passes, Wh = 32, E = 1.
    {
        const size_t CH  = (size_t)NBLK * THREADS;     // 65,536 chunks / pass
        const size_t NI8 = (size_t)EMB * NTOT / 8;     // 262,144 (Wi chunks)
        const size_t base = (size_t)blk * THREADS + tid;
#pragma unroll
        for (int i = 0; i < 4; i++) {
            size_t c = base + (size_t)i * CH;
            cvt8(Wi + c * 8, g_W + c * 8);
        }
#pragma unroll 8
        for (int i = 4; i < 36; i++) {
            size_t c = base + (size_t)i * CH;
            cvt8(Wh + (c - NI8) * 8, g_W + c * 8);
        }
        cvt8(E + base * 8, g_Ebf + base * 8);
    }
    // ---------- init state: block owns cols [blk*16, blk*16+16) of c/h ------
    {
        {   // 512 entries, one per thread
            int r = tid >> 4, q = tid & 15;
            size_t ci = (size_t)r * VOCAB + blk * 16 + q;
            g_c[ci] = 0.f;
            g_h[ci] = 0.f;
        }
        g_Hbf[0][blk * THREADS + tid] = __float2bfloat16(0.f);   // 512/block
        if (blk < 32 && tid < LAT)
            out[((size_t)blk * TSTEPS + 0) * LAT + tid] = 0.f;   // t=0 output
        if (tid < 64)
            bsm[tid] = bias[(tid >> 4) * 2048 + blk * 16 + (tid & 15)];
    }
    grid_sync();

    // ---------- step loop ----------
    for (int t = 1; t < TSTEPS; ++t) {
        const int nit = (t == 1) ? NITER1 : NITER;   // t=1: h==0 -> emb rows only

        // A-load mapping: row am (0..31), 8-elem chunk ac (0..15)
        const int am = tid >> 4, ac = tid & 15;
        const int v_am = __ldg(&tokens[am * TSTEPS + (t - 1)]);
        const __nv_bfloat16* a_emb = g_Ebf + (size_t)v_am * EMB;
        const __nv_bfloat16* a_h   = g_Hbf[(t - 1) & 1] + am * VOCAB;

        float acc[2][4];
#pragma unroll
        for (int i = 0; i < 2; i++)
#pragma unroll
            for (int j = 0; j < 4; j++) acc[i][j] = 0.f;

        auto issue_tile = [&](int st, int k0) {
            // A tile: 32 rows x 128 k (512 chunks, 1/thread)
            {
                const __nv_bfloat16* src = (k0 < EMB) ? (a_emb + k0 + ac * 8)
                                                      : (a_h + (k0 - EMB) + ac * 8);
                cp_async16(smem_u32(&Asm[st * ASTAGE + am * APITCH + ac * 8]), src);
            }
            // W tile: 128 k-rows x 64 cols (col = g*16+q): 1024 chunks, 2/thread
#pragma unroll
            for (int j2 = 0; j2 < 2; j2++) {
                int idx = tid + j2 * THREADS;
                int k = idx >> 3, rem = idx & 7;
                int g = rem >> 1, half = rem & 1;
                cp_async16(smem_u32(&Wsm[st * WSTAGE + k * WPITCH + g * 16 + half * 8]),
                           g_W + (size_t)(k0 + k) * NTOT + g * 2048 + blk * 16 + half * 8);
            }
        };

#pragma unroll
        for (int s = 0; s < STAGES - 1; ++s) {
            issue_tile(s, s * KTILE);
            asm volatile("cp.async.commit_group;\n");
        }

        for (int it = 0; it < nit; ++it) {
            asm volatile("cp.async.wait_group %0;\n" :: "n"(STAGES - 2));
            __syncthreads();    // all warps done with stage reuse; tile it ready

            if (it + STAGES - 1 < nit)
                issue_tile((it + STAGES - 1) & (STAGES - 1), (it + STAGES - 1) * KTILE);
            asm volatile("cp.async.commit_group;\n");

            const __nv_bfloat16* as = Asm + (it & (STAGES - 1)) * ASTAGE;
            const __nv_bfloat16* ws = Wsm + (it & (STAGES - 1)) * WSTAGE;
#pragma unroll
            for (int k2 = 0; k2 < 4; ++k2) {
                const int ks = kg * 4 + k2;
                uint32_t a[4];
                {
                    int row = mh * 16 + (lane & 15);
                    int col = ks * 16 + (lane >> 4) * 8;
                    ldsm_x4(a, smem_u32(&as[row * APITCH + col]));
                }
                uint32_t bq[4];
                {
                    int krow = ks * 16 + (lane & 15);
                    int col  = nq * 16 + (lane >> 4) * 8;
                    ldsm_x4_t(bq, smem_u32(&ws[krow * WPITCH + col]));
                }
                mma16816(acc[0], a, bq[0], bq[1]);
                mma16816(acc[1], a, bq[2], bq[3]);
            }
            // no trailing sync: next iteration's top sync protects buffer reuse
        }
        // drain ALL outstanding cp.async (t=1 leaves a real in-flight tile that
        // would otherwise race next step's prologue writes to the same stage)
        asm volatile("cp.async.wait_group 0;\n");
        __syncthreads();        // mainloop reads done before gsm alias

        // ---------- epilogue: 2-phase acc merge (kg split) -> gsm ----------
#pragma unroll
        for (int ns = 0; ns < 2; ++ns) {
            int row = mh * 16 + (lane >> 2);
            int col = nq * 16 + ns * 8 + (lane & 3) * 2;
            if (kg == 0) {
                *reinterpret_cast<float2*>(&gsm[row * GPITCH + col]) =
                    make_float2(acc[ns][0], acc[ns][1]);
                *reinterpret_cast<float2*>(&gsm[(row + 8) * GPITCH + col]) =
                    make_float2(acc[ns][2], acc[ns][3]);
            }
        }
        __syncthreads();
#pragma unroll
        for (int ns = 0; ns < 2; ++ns) {
            int row = mh * 16 + (lane >> 2);
            int col = nq * 16 + ns * 8 + (lane & 3) * 2;
            if (kg == 1) {
                float2* p0 = reinterpret_cast<float2*>(&gsm[row * GPITCH + col]);
                float2 v0 = *p0; v0.x += acc[ns][0]; v0.y += acc[ns][1]; *p0 = v0;
                float2* p1 = reinterpret_cast<float2*>(&gsm[(row + 8) * GPITCH + col]);
                float2 v1 = *p1; v1.x += acc[ns][2]; v1.y += acc[ns][3]; *p1 = v1;
            }
        }
        __syncthreads();

        // ---------- LSTM pointwise + partial sums: 1 (row,q) per thread ------
        {
            int r = tid >> 4, q = tid & 15;
            int v = __ldg(&tokens[r * TSTEPS + (t - 1)]);
            int s = __ldg(&tokens[r * TSTEPS + t]);
            bool upd = (v != 0);
            int n = blk * 16 + q;

            float gi = gsm[r * GPITCH + q]      + bsm[q];
            float gf = gsm[r * GPITCH + 16 + q] + bsm[16 + q];
            float gg = gsm[r * GPITCH + 32 + q] + bsm[32 + q];
            float go = gsm[r * GPITCH + 48 + q] + bsm[48 + q];
            float ia = fsig(gi), fa = fsig(gf);
            float ga = ftanh(gg), oa = fsig(go);
            size_t ci = (size_t)r * VOCAB + n;
            float cn = fa * g_c[ci] + ia * ga;
            float hn = oa * ftanh(cn);
            float h;
            if (upd) { g_c[ci] = cn; h = hn; g_h[ci] = h; }
            else     { h = g_h[ci]; }
            g_Hbf[t & 1][r * VOCAB + n] = __float2bfloat16(h);
            float e = __expf(h);               // |h|<1: no max shift needed
            float Z = e;
            float S = (n < s) ? e : ((n == s) ? 0.5f * e : 0.f);
            // reduce over the 16 lanes sharing a row (half-warp, xor-safe)
#pragma unroll
            for (int o = 1; o < 16; o <<= 1) {
                Z += __shfl_xor_sync(0xffffffffu, Z, o);
                S += __shfl_xor_sync(0xffffffffu, S, o);
            }
            if (q == 0) {
                g_partZ[t & 1][r * NBLK + blk] = Z;
                g_partS[t & 1][r * NBLK + blk] = S;
            }
        }

        grid_sync();   // h + partials visible everywhere

        // ---------- finalize (blocks 0..31) while others start next GEMM ----
        if (blk < 32) {
            if (tid < NBLK) {      // warps 0..3 (full warps)
                float Z = g_partZ[t & 1][blk * NBLK + tid];
                float S = g_partS[t & 1][blk * NBLK + tid];
#pragma unroll
                for (int o = 16; o; o >>= 1) {
                    Z += __shfl_xor_sync(0xffffffffu, Z, o);
                    S += __shfl_xor_sync(0xffffffffu, S, o);
                }
                if (lane == 0) { redz[warp] = Z; reds[warp] = S; }
            }
            __syncthreads();
            float Zt = redz[0] + redz[1] + redz[2] + redz[3];
            float St = reds[0] + reds[1] + reds[2] + reds[3];
            if (tid < LAT)
                out[((size_t)blk * TSTEPS + t) * LAT + tid] = 3.0f * St / Zt;
            __syncthreads();   // redz reuse safety for next t
        }
        // no second barrier: next step uses the other ping-pong slot; c/h is
        // block-private.
    }
}

// ---------------- launch ----------------------------------------------------
extern "C" void kernel_launch(void* const* d_in, const int* in_sizes, int n_in,
                              void* d_out, int out_size) {
    const int* tokens = nullptr;
    const float *E = nullptr, *Wi = nullptr, *Wh = nullptr, *bias = nullptr;
    for (int i = 0; i < n_in; i++) {
        switch (in_sizes[i]) {
            case BATCH * TSTEPS:      tokens = (const int*)d_in[i];   break;
            case VOCAB * EMB:         E      = (const float*)d_in[i]; break;
            case EMB * 4 * VOCAB:     Wi     = (const float*)d_in[i]; break;
            case VOCAB * 4 * VOCAB:   Wh     = (const float*)d_in[i]; break;
            case 4 * VOCAB:           bias   = (const float*)d_in[i]; break;
        }
    }
    float* out = (float*)d_out;

    // >48KB dynamic smem needs the opt-in attribute (host-side, capture-legal,
    // idempotent — called every launch, no static guards).
    cudaFuncSetAttribute(persistent_kernel,
                         cudaFuncAttributeMaxDynamicSharedMemorySize, SMEM_BYTES);
    persistent_kernel<<<NBLK, THREADS, SMEM_BYTES>>>(tokens, E, Wi, Wh, bias, out);
}